// round 10
// baseline (speedup 1.0000x reference)
#include <cuda_runtime.h>

typedef unsigned long long ull;

#define BATCH 131072
#define MTILE 64
#define NBLK  (BATCH / MTILE)
#define OUTY  ((size_t)BATCH * 64)

// h2 scratch between the two kernels (static __device__ allocation is the
// sanctioned scratch mechanism; no runtime alloc).
__device__ float g_h2[(size_t)BATCH * 512];

// ---------- f32x2 helpers ----------
__device__ __forceinline__ ull pk2(float a, float b) {
    ull r; asm("mov.b64 %0,{%1,%2};" : "=l"(r) : "f"(a), "f"(b)); return r;
}
__device__ __forceinline__ void up2(ull v, float &a, float &b) {
    asm("mov.b64 {%0,%1},%2;" : "=f"(a), "=f"(b) : "l"(v));
}
__device__ __forceinline__ void fma2(ull &d, ull a, ull b) {
    asm("fma.rn.f32x2 %0,%1,%2,%0;" : "+l"(d) : "l"(a), "l"(b));
}
struct __align__(16) U2 { ull a, b; };

// ---------- GEMM: C[64 x 256] += A[64 x K] @ W[K x 512][:, n0:n0+256] ----------
// acc[4][8] : rows r0..r0+3, cols n0+tc*16 .. +15 as f32x2 pairs.
// A in smem (row-major, stride lda). W staged gmem->smem [16][256] tiles,
// register-prefetch double buffering.
template <int K>
__device__ __forceinline__ void mm256(ull acc[4][8], const float* sA, int lda,
                                      const float* gW, int n0, float* wst,
                                      int tid, int r0, int tc) {
    const int kr = tid >> 4;
    const int cc = (tid & 15) << 4;
    const float* gsrc = gW + (size_t)kr * 512 + n0 + cc;
    float4 pf[4];
#pragma unroll
    for (int q = 0; q < 4; q++) pf[q] = *(const float4*)(gsrc + 4 * q);

#pragma unroll 1
    for (int t = 0; t < K / 16; t++) {
        __syncthreads();                       // prior consumers of wst done
        float4* wd = (float4*)(wst + kr * 256 + cc);
#pragma unroll
        for (int q = 0; q < 4; q++) wd[q] = pf[q];
        __syncthreads();                       // wst tile ready
        if (t + 1 < K / 16) {
            const float* gs = gsrc + (size_t)(t + 1) * 16 * 512;
#pragma unroll
            for (int q = 0; q < 4; q++) pf[q] = *(const float4*)(gs + 4 * q);
        }
#pragma unroll
        for (int kk = 0; kk < 16; kk++) {
            const int k = t * 16 + kk;
            float a0 = sA[(r0 + 0) * lda + k];
            float a1 = sA[(r0 + 1) * lda + k];
            float a2 = sA[(r0 + 2) * lda + k];
            float a3 = sA[(r0 + 3) * lda + k];
            ull aa[4] = { pk2(a0, a0), pk2(a1, a1), pk2(a2, a2), pk2(a3, a3) };
            const U2* bp = (const U2*)(wst + kk * 256 + tc * 16);
            U2 b0 = bp[0], b1 = bp[1], b2 = bp[2], b3 = bp[3];
            ull bs[8] = { b0.a, b0.b, b1.a, b1.b, b2.a, b2.b, b3.a, b3.b };
#pragma unroll
            for (int r = 0; r < 4; r++)
#pragma unroll
                for (int j = 0; j < 8; j++) fma2(acc[r][j], aa[r], bs[j]);
        }
    }
}

// ---------- Layer-3 GEMM: 192 padded cols (8 spline groups x 24) ----------
// Real W3 cols (8c+g)*23+jj for jj<23; padded col 23 of each group is zero.
__device__ __forceinline__ void mm192(ull acc[4][6], const float* sA,
                                      const float* W3, int chunk, float* wst,
                                      int tid, int r0, int tc) {
    int  goff[12]; bool gv[12];
#pragma unroll
    for (int i = 0; i < 12; i++) {
        int idx = tid + (i << 8);              // 0..3071 over [16][192]
        int kr = idx / 192, p = idx - kr * 192;
        int g = p / 24, jj = p - g * 24;
        gv[i]   = (jj < 23);
        goff[i] = kr * 736 + (chunk * 8 + g) * 23 + jj;
    }
    float pf[12];
#pragma unroll
    for (int i = 0; i < 12; i++) pf[i] = gv[i] ? W3[(size_t)goff[i]] : 0.f;

#pragma unroll 1
    for (int t = 0; t < 32; t++) {
        __syncthreads();
#pragma unroll
        for (int i = 0; i < 12; i++) wst[tid + (i << 8)] = pf[i];
        __syncthreads();
        if (t + 1 < 32) {
            const float* gs = W3 + (size_t)(t + 1) * 16 * 736;
#pragma unroll
            for (int i = 0; i < 12; i++) pf[i] = gv[i] ? gs[goff[i]] : 0.f;
        }
#pragma unroll
        for (int kk = 0; kk < 16; kk++) {
            const int k = t * 16 + kk;
            float a0 = sA[(r0 + 0) * 512 + k];
            float a1 = sA[(r0 + 1) * 512 + k];
            float a2 = sA[(r0 + 2) * 512 + k];
            float a3 = sA[(r0 + 3) * 512 + k];
            ull aa[4] = { pk2(a0, a0), pk2(a1, a1), pk2(a2, a2), pk2(a3, a3) };
            const U2* bp = (const U2*)(wst + kk * 192 + tc * 12);
            U2 b0 = bp[0], b1 = bp[1], b2 = bp[2];
            ull bs[6] = { b0.a, b0.b, b1.a, b1.b, b2.a, b2.b };
#pragma unroll
            for (int r = 0; r < 4; r++)
#pragma unroll
                for (int j = 0; j < 6; j++) fma2(acc[r][j], aa[r], bs[j]);
        }
    }
}

// ---------- kernel A: layers 1+2 -> g_h2 ----------
// smem: hs[64][512]=32768f | wst[16][256]=4096f | xms[64][32]=2048f  (152 KB)
__global__ void __launch_bounds__(256, 1)
kA(const float* __restrict__ x,
   const float* __restrict__ W1, const float* __restrict__ b1,
   const float* __restrict__ W2, const float* __restrict__ b2) {
    extern __shared__ float sm[];
    float* hs  = sm;
    float* wst = sm + 32768;
    float* xms = sm + 36864;
    const int tid = threadIdx.x;
    const int m0  = blockIdx.x * MTILE;
    const int r0  = (tid >> 4) << 2;
    const int tc  = tid & 15;

    // load x_masked (cols 0..31) into smem
    for (int i = tid; i < 512; i += 256) {
        int row = i >> 3, q = i & 7;
        float4 v = *(const float4*)(x + (size_t)(m0 + row) * 64 + 4 * q);
        *(float4*)(xms + row * 32 + 4 * q) = v;
    }
    // (mm256's leading __syncthreads orders xms writes before reads)

    // ---- layer 1: h1 = relu(xm @ W1 + b1) -> hs ----
#pragma unroll 1
    for (int p = 0; p < 2; p++) {
        const int n0 = p * 256;
        ull acc[4][8];
#pragma unroll
        for (int j = 0; j < 8; j++) {
            float2 bb = *(const float2*)(b1 + n0 + tc * 16 + 2 * j);
            ull bi = pk2(bb.x, bb.y);
#pragma unroll
            for (int r = 0; r < 4; r++) acc[r][j] = bi;
        }
        mm256<32>(acc, xms, 32, W1, n0, wst, tid, r0, tc);
#pragma unroll
        for (int r = 0; r < 4; r++)
#pragma unroll
            for (int j = 0; j < 8; j++) {
                float v0, v1; up2(acc[r][j], v0, v1);
                *(ull*)(hs + (r0 + r) * 512 + n0 + tc * 16 + 2 * j) =
                    pk2(fmaxf(v0, 0.f), fmaxf(v1, 0.f));
            }
    }

    // ---- layer 2: h2 = relu(h1 @ W2 + b2) -> gmem scratch ----
#pragma unroll 1
    for (int p = 0; p < 2; p++) {
        const int n0 = p * 256;
        ull acc[4][8];
#pragma unroll
        for (int j = 0; j < 8; j++) {
            float2 bb = *(const float2*)(b2 + n0 + tc * 16 + 2 * j);
            ull bi = pk2(bb.x, bb.y);
#pragma unroll
            for (int r = 0; r < 4; r++) acc[r][j] = bi;
        }
        mm256<512>(acc, hs, 512, W2, n0, wst, tid, r0, tc);
#pragma unroll
        for (int r = 0; r < 4; r++) {
            float4 o[4];
#pragma unroll
            for (int j = 0; j < 8; j++) {
                float v0, v1; up2(acc[r][j], v0, v1);
                ((float*)o)[2 * j]     = fmaxf(v0, 0.f);
                ((float*)o)[2 * j + 1] = fmaxf(v1, 0.f);
            }
            float4* dst = (float4*)(g_h2 + (size_t)(m0 + r0 + r) * 512 + n0 + tc * 16);
#pragma unroll
            for (int q = 0; q < 4; q++) dst[q] = o[q];
        }
    }
}

// ---------- kernel B: layer 3 + RQ spline + outputs ----------
// smem: hs 32768f | wst 3072f | raw 12288f | xt 2048f | ldp 2112f = 52288f (204 KB)
__global__ void __launch_bounds__(256, 1)
kB(const float* __restrict__ x, const float* __restrict__ W3,
   const float* __restrict__ b3, float* __restrict__ out) {
    extern __shared__ float sm[];
    float* hs  = sm;
    float* wst = sm + 32768;
    float* raw = sm + 35840;
    float* xt  = sm + 48128;
    float* ldp = sm + 50176;   // [64][33] padded, conflict-free
    const int tid = threadIdx.x;
    const int m0  = blockIdx.x * MTILE;
    const int r0  = (tid >> 4) << 2;
    const int tc  = tid & 15;

    // load h2 tile (fully coalesced float4)
    const float4* hsrc = (const float4*)(g_h2 + (size_t)m0 * 512);
    float4* hd4 = (float4*)hs;
#pragma unroll 8
    for (int i = 0; i < 32; i++) hd4[tid + 256 * i] = hsrc[tid + 256 * i];

    // x tile: cols 0..31 passthrough -> out, cols 32..63 -> xt
    for (int i = tid; i < 1024; i += 256) {
        int row = i >> 4, q = i & 15;
        float4 v = *(const float4*)(x + (size_t)(m0 + row) * 64 + 4 * q);
        if (q < 8) *(float4*)(out + (size_t)(m0 + row) * 64 + 4 * q) = v;
        else       *(float4*)(xt + row * 32 + 4 * (q - 8)) = v;
    }

#pragma unroll 1
    for (int c = 0; c < 4; c++) {
        // bias init (padded col of each 24-group = 0)
        ull acc[4][6];
#pragma unroll
        for (int j = 0; j < 6; j++) {
            int p = tc * 12 + 2 * j;
            int g0 = p / 24,       j0 = p - g0 * 24;
            int g1 = (p + 1) / 24, j1 = (p + 1) - g1 * 24;
            float v0 = (j0 < 23) ? b3[(c * 8 + g0) * 23 + j0] : 0.f;
            float v1 = (j1 < 23) ? b3[(c * 8 + g1) * 23 + j1] : 0.f;
            ull bi = pk2(v0, v1);
#pragma unroll
            for (int r = 0; r < 4; r++) acc[r][j] = bi;
        }
        mm192(acc, hs, W3, c, wst, tid, r0, tc);

        // raw tile -> smem for the per-dim reshuffle
#pragma unroll
        for (int r = 0; r < 4; r++)
#pragma unroll
            for (int j = 0; j < 6; j++)
                *(ull*)(raw + (r0 + r) * 192 + tc * 12 + 2 * j) = acc[r][j];
        __syncthreads();

        // spline epilogue: 512 (row,dim) tasks, 2 per thread
#pragma unroll 1
        for (int i = 0; i < 2; i++) {
            int task = tid + 256 * i;
            int row = task >> 3, g = task & 7;
            const float* rb = raw + row * 192 + g * 24;
            float xv = xt[row * 32 + c * 8 + g];

            float wr[8], hr[8];
#pragma unroll
            for (int q = 0; q < 8; q++) { wr[q] = rb[q]; hr[q] = rb[8 + q]; }
            float mw = wr[0], mh = hr[0];
#pragma unroll
            for (int q = 1; q < 8; q++) { mw = fmaxf(mw, wr[q]); mh = fmaxf(mh, hr[q]); }
            float sw = 0.f, sh = 0.f;
#pragma unroll
            for (int q = 0; q < 8; q++) {
                wr[q] = expf(wr[q] - mw); sw += wr[q];
                hr[q] = expf(hr[q] - mh); sh += hr[q];
            }
            float fw = 6.f / sw, fh = 6.f / sh;
#pragma unroll
            for (int q = 0; q < 8; q++) { wr[q] *= fw; hr[q] *= fh; }

            float dv[9]; dv[0] = 1.f; dv[8] = 1.f;
#pragma unroll
            for (int q = 0; q < 7; q++) {
                float v = rb[16 + q];
                dv[q + 1] = fmaxf(v, 0.f) + log1pf(expf(-fabsf(v)));   // softplus
            }
            float cw[9], ch[9]; cw[0] = -3.f; ch[0] = -3.f;
#pragma unroll
            for (int q = 0; q < 8; q++) { cw[q + 1] = cw[q] + wr[q]; ch[q + 1] = ch[q] + hr[q]; }

            float xc = fminf(fmaxf(xv, -3.f + 1e-6f), 3.f - 1e-6f);
            int bin = 0;
#pragma unroll
            for (int q = 1; q < 9; q++) bin += (cw[q] < xc) ? 1 : 0;
            bin = min(bin, 7);

            // register gathers via unrolled selects (no local-mem spill)
            float wk = wr[0], hk = hr[0], dk = dv[0], dk1 = dv[1];
            float cwk = cw[0], chk = ch[0];
#pragma unroll
            for (int q = 1; q < 8; q++) {
                bool s = (bin >= q);
                wk  = s ? wr[q] : wk;   hk  = s ? hr[q] : hk;
                dk  = s ? dv[q] : dk;   dk1 = s ? dv[q + 1] : dk1;
                cwk = s ? cw[q] : cwk;  chk = s ? ch[q] : chk;
            }
            float xi = fminf(fmaxf((xc - cwk) / wk, 1e-6f), 1.f - 1e-6f);
            float s  = hk / wk;
            float om = 1.f - xi;
            float num = hk * (s * xi * xi + dk * xi * om);
            float den = s + (dk + dk1 - 2.f * s) * xi * om;
            float yin = chk + num / den;
            float t1  = s * s * (dk1 * xi * xi + 2.f * s * xi * om + dk * om * om);
            float ldin = logf(t1 + 1e-8f) - logf(den * den + 1e-8f);
            bool inside = (xv >= -3.f) && (xv <= 3.f);
            int dim = c * 8 + g;
            out[(size_t)(m0 + row) * 64 + 32 + dim] = inside ? yin : xv;
            ldp[row * 33 + dim] = inside ? ldin : 0.f;
        }
        __syncthreads();
    }

    // log_det reduction per row (deterministic, conflict-free)
    if (tid < 64) {
        float s = 0.f;
#pragma unroll
        for (int d = 0; d < 32; d++) s += ldp[tid * 33 + d];
        out[OUTY + m0 + tid] = s;
    }
}

extern "C" void kernel_launch(void* const* d_in, const int* in_sizes, int n_in,
                              void* d_out, int out_size) {
    const float* x  = (const float*)d_in[0];
    const float* W1 = (const float*)d_in[1];
    const float* b1 = (const float*)d_in[2];
    const float* W2 = (const float*)d_in[3];
    const float* b2 = (const float*)d_in[4];
    const float* W3 = (const float*)d_in[5];
    const float* b3 = (const float*)d_in[6];
    float* out = (float*)d_out;

    const size_t smA = 38912u * 4u;   // 152 KB
    const size_t smB = 52288u * 4u;   // 204 KB
    cudaFuncSetAttribute(kA, cudaFuncAttributeMaxDynamicSharedMemorySize, (int)smA);
    cudaFuncSetAttribute(kB, cudaFuncAttributeMaxDynamicSharedMemorySize, (int)smB);

    kA<<<NBLK, 256, smA>>>(x, W1, b1, W2, b2);
    kB<<<NBLK, 256, smB>>>(x, W3, b3, out);
}

// round 17
// speedup vs baseline: 2.4724x; 2.4724x over previous
#include <cuda_runtime.h>
#include <cuda_bf16.h>
typedef unsigned u32; typedef __nv_bfloat16 bf;
#define C2B __float2bfloat16
#define B2F __bfloat162float
#define OUTY ((size_t)131072*64)

// packed weight/activation images (static device scratch is sanctioned)
__device__ u32   g_W1p[48*520];
__device__ u32   g_W2p[768*520];
__device__ u32   g_W3p[768*776];
__device__ float g_b3p[768];
__device__ u32   g_h1[(size_t)131072*772];
__device__ u32   g_h2[(size_t)131072*772];
__device__ float g_raw[(size_t)131072*768];

__device__ __forceinline__ u32 s2u(const void* p){u32 a;asm("{.reg .u64 t;cvta.to.shared.u64 t,%1;cvt.u32.u64 %0,t;}":"=r"(a):"l"(p));return a;}
__device__ __forceinline__ u32 pkb(float x,float y){
  return (u32)__bfloat16_as_ushort(C2B(x)) | ((u32)__bfloat16_as_ushort(C2B(y))<<16);}
__device__ __forceinline__ u32 plo2(float x,float y){
  float hx=B2F(C2B(x)), hy=B2F(C2B(y)); return pkb(x-hx,y-hy);}
__device__ __forceinline__ void cpa(u32 d,const void* s){
  asm volatile("cp.async.ca.shared.global [%0],[%1],16;"::"r"(d),"l"(s));}
__device__ __forceinline__ void cpc(){asm volatile("cp.async.commit_group;");}
template<int N> __device__ __forceinline__ void cpw(){asm volatile("cp.async.wait_group %0;"::"n"(N));}
__device__ __forceinline__ void mma16(float c[4],u32 a0,u32 a1,u32 a2,u32 a3,u32 b0,u32 b1){
  asm volatile("mma.sync.aligned.m16n8k16.row.col.f32.bf16.bf16.f32 "
    "{%0,%1,%2,%3},{%4,%5,%6,%7},{%8,%9},{%0,%1,%2,%3};"
    :"+f"(c[0]),"+f"(c[1]),"+f"(c[2]),"+f"(c[3])
    :"r"(a0),"r"(a1),"r"(a2),"r"(a3),"r"(b0),"r"(b1));}

// NST k16-steps from smem. A stride STA (words), B stride 136.
// aB=(wm*64+g)*STA+c ; bB=c*136+wn*64+g
template<int STA,int NST>
__device__ __forceinline__ void steps(const u32* sA,const u32* sB,float C[4][8][4],int aB,int bB){
#pragma unroll
  for(int st=0;st<NST;st++){
    u32 a[4][4];
#pragma unroll
    for(int mt=0;mt<4;mt++){
      const u32* ap=sA+aB+mt*16*STA+st*8;
      a[mt][0]=ap[0]; a[mt][1]=ap[8*STA]; a[mt][2]=ap[4]; a[mt][3]=ap[8*STA+4];
    }
#pragma unroll
    for(int nt=0;nt<8;nt++){
      const u32* bp=sB+bB+st*8*136+nt*8;
      u32 b0=bp[0], b1=bp[4*136];
#pragma unroll
      for(int mt=0;mt<4;mt++) mma16(C[mt][nt],a[mt][0],a[mt][1],a[mt][2],a[mt][3],b0,b1);
    }
  }
}

// load one k64-chunk (32 pairs): A 256x32 words (dst stride 36), B 32x128 (dst stride 136)
template<int SB>
__device__ __forceinline__ void ldchunk(const u32* gA,const u32* gB,int n0,int cc,int sel,u32 smb,int tid){
  const u32* as=gA+(size_t)tid*772+cc*32;
  u32 ad=smb+(u32)(sel*9216+tid*36)*4u;
#pragma unroll
  for(int q=0;q<8;q++) cpa(ad+q*16,as+q*4);
#pragma unroll
  for(int q=0;q<4;q++){
    int j=tid+q*256, p=j>>5, sg=j&31;
    cpa(smb+(u32)(18432+sel*4352+p*136+sg*4)*4u, gB+(size_t)(cc*32+p)*SB+n0+sg*4);
  }
  cpc();
}

// full K'=1536 pass: 24 chunks, double buffered
template<int SB>
__device__ __forceinline__ void gemm256(const u32* gA,const u32* gB,int n0,float C[4][8][4],
                                        u32* sm,int tid,int aB,int bB){
  u32 smb=s2u(sm);
  ldchunk<SB>(gA,gB,n0,0,0,smb,tid);
#pragma unroll 1
  for(int cc=0;cc<24;cc++){
    if(cc<23){ ldchunk<SB>(gA,gB,n0,cc+1,(cc+1)&1,smb,tid); cpw<1>(); }
    else cpw<0>();
    __syncthreads();
    int sel=cc&1;
    steps<36,4>(sm+sel*9216, sm+18432+sel*4352, C, aB, bB);
    __syncthreads();
  }
}

// relu + bf16 split -> packed h image [Ah|Al|Ah], row stride 772
__device__ __forceinline__ void epiH(float C[4][8][4],const float* __restrict__ bias,u32* gH,
                                     size_t m0,int n0,int wm,int wn,int g,int c){
#pragma unroll
  for(int mt=0;mt<4;mt++)
#pragma unroll
  for(int nt=0;nt<8;nt++){
    int col=n0+wn*64+nt*8+2*c, pn=col>>1;
    float b0=bias[col], b1=bias[col+1];
#pragma unroll
    for(int rr=0;rr<2;rr++){
      int row=wm*64+mt*16+g+rr*8;
      float f0=fmaxf(C[mt][nt][rr*2]+b0,0.f), f1=fmaxf(C[mt][nt][rr*2+1]+b1,0.f);
      u32* hr=gH+(m0+row)*772;
      hr[pn]=pkb(f0,f1); hr[256+pn]=plo2(f0,f1); hr[512+pn]=pkb(f0,f1);
    }
  }
}

// ---------------- kp: pack weights ----------------
__global__ void kp(const float* __restrict__ W1,const float* __restrict__ W2,
                   const float* __restrict__ W3,const float* __restrict__ b3){
  int i=blockIdx.x*512+threadIdx.x;
  if(i<24960){                                   // W1p [48][520]
    int p=i/520,n=i-p*520;
    if(n>=512){g_W1p[i]=0;return;}
    int s=p>>4,k=2*(p&15);
    float v0=W1[k*512+n],v1=W1[(k+1)*512+n];
    g_W1p[i]=(s==2)?plo2(v0,v1):pkb(v0,v1);
  }else if(i<424320){                            // W2p [768][520]
    int j=i-24960,p=j/520,n=j-p*520;
    if(n>=512){g_W2p[j]=0;return;}
    int s=p>>8,k=2*(p&255);
    float v0=W2[k*512+n],v1=W2[(k+1)*512+n];
    g_W2p[j]=(s==2)?plo2(v0,v1):pkb(v0,v1);
  }else if(i<1020288){                           // W3p [768][776]
    int j=i-424320,p=j/776,n=j-p*776;
    if(n>=768){g_W3p[j]=0;return;}
    int d=n/24,jj=n-d*24,s=p>>8,k=2*(p&255);
    float v0=0.f,v1=0.f;
    if(jj<23){v0=W3[k*736+d*23+jj];v1=W3[(k+1)*736+d*23+jj];}
    g_W3p[j]=(s==2)?plo2(v0,v1):pkb(v0,v1);
  }else if(i<1021056){                           // b3p [768]
    int n=i-1020288,d=n/24,jj=n-d*24;
    g_b3p[n]=(jj<23)?b3[d*23+jj]:0.f;
  }
}

// ---------------- k1: x_masked -> h1 (K'=96) ----------------
__global__ void __launch_bounds__(256) k1k(const float* __restrict__ x,const float* __restrict__ b1){
  extern __shared__ u32 sm[];                     // A' 256*52=13312 | B 48*136=6528
  int tid=threadIdx.x,w=tid>>5,l=tid&31,g=l>>2,c=l&3,wm=w&3,wn=w>>2;
  size_t m0=(size_t)blockIdx.x*256;
  u32 smb=s2u(sm);
  {                                               // build A' in smem (thread = row)
    const float4* xr=(const float4*)(x+(m0+tid)*64);
    float v[32];
#pragma unroll
    for(int q=0;q<8;q++){float4 t4=xr[q];v[4*q]=t4.x;v[4*q+1]=t4.y;v[4*q+2]=t4.z;v[4*q+3]=t4.w;}
    u32* ar=sm+tid*52;
#pragma unroll
    for(int p=0;p<16;p++){
      u32 hw=pkb(v[2*p],v[2*p+1]);
      ar[p]=hw; ar[32+p]=hw; ar[16+p]=plo2(v[2*p],v[2*p+1]);
    }
  }
  int aB=(wm*64+g)*52+c, bB=c*136+wn*64+g;
#pragma unroll 1
  for(int pass=0;pass<4;pass++){
    int n0=pass*128;
    __syncthreads();                              // A' ready / previous pass B reads done
#pragma unroll
    for(int q=0;q<6;q++){
      int j=tid+q*256,p=j>>5,sg=j&31;
      cpa(smb+(u32)(13312+p*136+sg*4)*4u, g_W1p+(size_t)p*520+n0+sg*4);
    }
    cpc(); cpw<0>(); __syncthreads();
    float C[4][8][4];
#pragma unroll
    for(int a=0;a<4;a++)
#pragma unroll
    for(int b=0;b<8;b++)
#pragma unroll
    for(int d=0;d<4;d++) C[a][b][d]=0.f;
    steps<52,6>(sm, sm+13312, C, aB, bB);
    epiH(C,b1,g_h1,m0,n0,wm,wn,g,c);
  }
}

// ---------------- k2: h1 -> h2 ----------------
__global__ void __launch_bounds__(256) k2k(const float* __restrict__ b2){
  extern __shared__ u32 sm[];
  int tid=threadIdx.x,w=tid>>5,l=tid&31,g=l>>2,c=l&3,wm=w&3,wn=w>>2;
  size_t m0=(size_t)blockIdx.x*256;
  int aB=(wm*64+g)*36+c, bB=c*136+wn*64+g;
#pragma unroll 1
  for(int pass=0;pass<4;pass++){
    int n0=pass*128;
    float C[4][8][4];
#pragma unroll
    for(int a=0;a<4;a++)
#pragma unroll
    for(int b=0;b<8;b++)
#pragma unroll
    for(int d=0;d<4;d++) C[a][b][d]=0.f;
    gemm256<520>(g_h1+m0*772,g_W2p,n0,C,sm,tid,aB,bB);
    epiH(C,b2,g_h2,m0,n0,wm,wn,g,c);
    __syncthreads();
  }
}

// ---------------- k3: h2 -> raw (bias added) ----------------
__global__ void __launch_bounds__(256) k3k(){
  extern __shared__ u32 sm[];
  int tid=threadIdx.x,w=tid>>5,l=tid&31,g=l>>2,c=l&3,wm=w&3,wn=w>>2;
  size_t m0=(size_t)blockIdx.x*256;
  int aB=(wm*64+g)*36+c, bB=c*136+wn*64+g;
#pragma unroll 1
  for(int pass=0;pass<6;pass++){
    int n0=pass*128;
    float C[4][8][4];
#pragma unroll
    for(int a=0;a<4;a++)
#pragma unroll
    for(int b=0;b<8;b++)
#pragma unroll
    for(int d=0;d<4;d++) C[a][b][d]=0.f;
    gemm256<776>(g_h2+m0*772,g_W3p,n0,C,sm,tid,aB,bB);
#pragma unroll
    for(int mt=0;mt<4;mt++)
#pragma unroll
    for(int nt=0;nt<8;nt++){
      int col=n0+wn*64+nt*8+2*c;
      float b0=g_b3p[col], b1=g_b3p[col+1];
#pragma unroll
      for(int rr=0;rr<2;rr++){
        int row=wm*64+mt*16+g+rr*8;
        float2 v=make_float2(C[mt][nt][rr*2]+b0, C[mt][nt][rr*2+1]+b1);
        *(float2*)&g_raw[(m0+row)*768+col]=v;
      }
    }
    __syncthreads();
  }
}

// ---------------- k4: RQ spline + outputs (verified R5 math) ----------------
__global__ void __launch_bounds__(256) k4k(const float* __restrict__ x,float* __restrict__ out){
  __shared__ float xt[64*32];
  __shared__ float ldp[64*33];
  int tid=threadIdx.x;
  size_t m0=(size_t)blockIdx.x*64;
  for(int i=tid;i<1024;i+=256){
    int row=i>>4,q=i&15;
    float4 v=*(const float4*)(x+(m0+row)*64+4*q);
    if(q<8)*(float4*)(out+(m0+row)*64+4*q)=v;
    else   *(float4*)(xt+row*32+4*(q-8))=v;
  }
  __syncthreads();
#pragma unroll 1
  for(int i=0;i<8;i++){
    int task=tid+256*i, row=task>>5, d=task&31;
    const float* rb=g_raw+(m0+row)*768+d*24;
    float xv=xt[row*32+d];
    float wr[8],hr[8];
#pragma unroll
    for(int q=0;q<8;q++){wr[q]=rb[q];hr[q]=rb[8+q];}
    float mw=wr[0],mh=hr[0];
#pragma unroll
    for(int q=1;q<8;q++){mw=fmaxf(mw,wr[q]);mh=fmaxf(mh,hr[q]);}
    float sw=0.f,sh=0.f;
#pragma unroll
    for(int q=0;q<8;q++){wr[q]=expf(wr[q]-mw);sw+=wr[q];hr[q]=expf(hr[q]-mh);sh+=hr[q];}
    float fw=6.f/sw,fh=6.f/sh;
#pragma unroll
    for(int q=0;q<8;q++){wr[q]*=fw;hr[q]*=fh;}
    float dv[9]; dv[0]=1.f; dv[8]=1.f;
#pragma unroll
    for(int q=0;q<7;q++){float vv=rb[16+q]; dv[q+1]=fmaxf(vv,0.f)+log1pf(expf(-fabsf(vv)));}
    float cw[9],ch[9]; cw[0]=-3.f; ch[0]=-3.f;
#pragma unroll
    for(int q=0;q<8;q++){cw[q+1]=cw[q]+wr[q];ch[q+1]=ch[q]+hr[q];}
    float xc=fminf(fmaxf(xv,-3.f+1e-6f),3.f-1e-6f);
    int bin=0;
#pragma unroll
    for(int q=1;q<9;q++) bin+=(cw[q]<xc)?1:0;
    bin=min(bin,7);
    float wk=wr[0],hk=hr[0],dk=dv[0],dk1=dv[1],cwk=cw[0],chk=ch[0];
#pragma unroll
    for(int q=1;q<8;q++){bool s=(bin>=q);
      wk=s?wr[q]:wk; hk=s?hr[q]:hk; dk=s?dv[q]:dk; dk1=s?dv[q+1]:dk1;
      cwk=s?cw[q]:cwk; chk=s?ch[q]:chk;}
    float xi=fminf(fmaxf((xc-cwk)/wk,1e-6f),1.f-1e-6f);
    float s=hk/wk, om=1.f-xi;
    float num=hk*(s*xi*xi+dk*xi*om);
    float den=s+(dk+dk1-2.f*s)*xi*om;
    float yin=chk+num/den;
    float t1=s*s*(dk1*xi*xi+2.f*s*xi*om+dk*om*om);
    float ldin=logf(t1+1e-8f)-logf(den*den+1e-8f);
    bool inside=(xv>=-3.f)&&(xv<=3.f);
    out[(m0+row)*64+32+d]=inside?yin:xv;
    ldp[row*33+d]=inside?ldin:0.f;
  }
  __syncthreads();
  if(tid<64){
    float s=0.f;
#pragma unroll
    for(int d=0;d<32;d++) s+=ldp[tid*33+d];
    out[OUTY+m0+tid]=s;
  }
}

extern "C" void kernel_launch(void* const* d_in,const int* in_sizes,int n_in,
                              void* d_out,int out_size){
  const float* x =(const float*)d_in[0];
  const float* W1=(const float*)d_in[1];
  const float* b1=(const float*)d_in[2];
  const float* W2=(const float*)d_in[3];
  const float* b2=(const float*)d_in[4];
  const float* W3=(const float*)d_in[5];
  const float* b3=(const float*)d_in[6];
  float* out=(float*)d_out;
  const int sm1=(13312+6528)*4;      // 79,360 B
  const int sm2=(18432+2*4352)*4;    // 108,544 B
  cudaFuncSetAttribute(k1k,cudaFuncAttributeMaxDynamicSharedMemorySize,sm1);
  cudaFuncSetAttribute(k2k,cudaFuncAttributeMaxDynamicSharedMemorySize,sm2);
  cudaFuncSetAttribute(k3k,cudaFuncAttributeMaxDynamicSharedMemorySize,sm2);
  kp <<<1995,512>>>(W1,W2,W3,b3);
  k1k<<<512,256,sm1>>>(x,b1);
  k2k<<<512,256,sm2>>>(b2);
  k3k<<<512,256,sm2>>>();
  k4k<<<2048,256>>>(x,out);
}